// round 5
// baseline (speedup 1.0000x reference)
#include <cuda_runtime.h>
#include <cuda_bf16.h>
#include <math.h>
#include <stdint.h>

#define BB 2
#define SS 4096
#define DD 128
#define HALF 64
#define TQ 32
#define KROWS (TQ + 2*HALF)   /* 160 */
#define PW 136
#define PWARP (4*PW)
#define NEG_INF_F (-1e30f)

__device__ float g_q[BB*SS*DD];
__device__ float g_k[BB*SS*DD];
__device__ float g_v[BB*SS*DD];

// ===================== QKV via mma.sync bf16 (HMMA path) =====================
// 128 CTAs x 64 rows. D = x_hi@W_hi + x_hi@W_lo + x_lo@W_hi (Dekker split).

#define S136 136                       /* bf16 elems per smem row (272 B) */
#define XTILE_B (64  * S136 * 2)       /* 17408 */
#define WTILE_B (128 * S136 * 2)       /* 34816 */
#define OFF_XHI 0
#define OFF_XLO (OFF_XHI + XTILE_B)
#define OFF_WHI (OFF_XLO + XTILE_B)
#define OFF_WLO (OFF_WHI + WTILE_B)
#define QKV_SMEM (OFF_WLO + WTILE_B)   /* 104448 */

__device__ __forceinline__ void mma16816(float* d, const uint32_t* a,
                                         const uint32_t* b) {
    asm volatile(
        "mma.sync.aligned.m16n8k16.row.col.f32.bf16.bf16.f32 "
        "{%0,%1,%2,%3}, {%4,%5,%6,%7}, {%8,%9}, {%0,%1,%2,%3};\n"
        : "+f"(d[0]), "+f"(d[1]), "+f"(d[2]), "+f"(d[3])
        : "r"(a[0]), "r"(a[1]), "r"(a[2]), "r"(a[3]), "r"(b[0]), "r"(b[1]));
}

__device__ __forceinline__ __nv_bfloat162 split_hi2(float x, float y) {
    return __nv_bfloat162(__float2bfloat16(x), __float2bfloat16(y));
}
__device__ __forceinline__ __nv_bfloat162 split_lo2(float x, float y) {
    float hx = __bfloat162float(__float2bfloat16(x));
    float hy = __bfloat162float(__float2bfloat16(y));
    return __nv_bfloat162(__float2bfloat16(x - hx), __float2bfloat16(y - hy));
}

__global__ void __launch_bounds__(256) qkv_mma_kernel(
    const float* __restrict__ x,
    const float* __restrict__ Wq, const float* __restrict__ bq,
    const float* __restrict__ Wk, const float* __restrict__ bk,
    const float* __restrict__ Wv, const float* __restrict__ bv)
{
    extern __shared__ char sb[];
    const int tid  = threadIdx.x;
    const int wid  = tid >> 5;
    const int lane = tid & 31;
    const int row0 = blockIdx.x * 64;

    // ---- convert x tile: 64x128 fp32 -> hi/lo bf16, row stride S136 ----
    for (int idx = tid; idx < 64 * 64; idx += 256) {
        int r = idx >> 6, k = (idx & 63) << 1;
        float2 v = *(const float2*)(x + (size_t)(row0 + r) * DD + k);
        int off = (r * S136 + k) * 2;
        *(__nv_bfloat162*)(sb + OFF_XHI + off) = split_hi2(v.x, v.y);
        *(__nv_bfloat162*)(sb + OFF_XLO + off) = split_lo2(v.x, v.y);
    }

    const float* Wm[3]   = {Wq, Wk, Wv};
    const float* bias[3] = {bq, bk, bv};
    float* outm[3];
    outm[0] = g_q; outm[1] = g_k; outm[2] = g_v;

    const int mw = wid & 1;     // M group (32 rows)
    const int nw = wid >> 1;    // N group (32 cols)
    const int ar = lane >> 2;   // fragment row within 8
    const int ac = (lane & 3) << 2;  // fragment byte col offset

    for (int m = 0; m < 3; ++m) {
        if (m > 0) __syncthreads();   // prior matrix's mma reads done

        // ---- convert W transposed: Wt[n][k] = W[k][n], hi/lo ----
        const float* Wg = Wm[m];
        for (int idx = tid; idx < 128 * 32; idx += 256) {
            int n = idx >> 5, k4 = (idx & 31) << 2;
            float w0 = __ldg(Wg + (size_t)(k4 + 0) * DD + n);
            float w1 = __ldg(Wg + (size_t)(k4 + 1) * DD + n);
            float w2 = __ldg(Wg + (size_t)(k4 + 2) * DD + n);
            float w3 = __ldg(Wg + (size_t)(k4 + 3) * DD + n);
            int off = (n * S136 + k4) * 2;
            *(__nv_bfloat162*)(sb + OFF_WHI + off)     = split_hi2(w0, w1);
            *(__nv_bfloat162*)(sb + OFF_WHI + off + 4) = split_hi2(w2, w3);
            *(__nv_bfloat162*)(sb + OFF_WLO + off)     = split_lo2(w0, w1);
            *(__nv_bfloat162*)(sb + OFF_WLO + off + 4) = split_lo2(w2, w3);
        }
        __syncthreads();

        // ---- mma mainloop: warp tile M32 x N32, K=128 in 8 steps ----
        float acc[2][4][4];
        #pragma unroll
        for (int mt = 0; mt < 2; ++mt)
            #pragma unroll
            for (int nt = 0; nt < 4; ++nt)
                #pragma unroll
                for (int e = 0; e < 4; ++e) acc[mt][nt][e] = 0.f;

        #pragma unroll
        for (int ks = 0; ks < 8; ++ks) {
            const int kb = ks * 32;    // byte offset of k0 within row
            uint32_t ahi[2][4], alo[2][4];
            #pragma unroll
            for (int mt = 0; mt < 2; ++mt) {
                int abase = (mw * 32 + mt * 16 + ar) * 272 + kb + ac;
                ahi[mt][0] = *(const uint32_t*)(sb + OFF_XHI + abase);
                ahi[mt][1] = *(const uint32_t*)(sb + OFF_XHI + abase + 8*272);
                ahi[mt][2] = *(const uint32_t*)(sb + OFF_XHI + abase + 16);
                ahi[mt][3] = *(const uint32_t*)(sb + OFF_XHI + abase + 8*272 + 16);
                alo[mt][0] = *(const uint32_t*)(sb + OFF_XLO + abase);
                alo[mt][1] = *(const uint32_t*)(sb + OFF_XLO + abase + 8*272);
                alo[mt][2] = *(const uint32_t*)(sb + OFF_XLO + abase + 16);
                alo[mt][3] = *(const uint32_t*)(sb + OFF_XLO + abase + 8*272 + 16);
            }
            #pragma unroll
            for (int nt = 0; nt < 4; ++nt) {
                int bbase = (nw * 32 + nt * 8 + ar) * 272 + kb + ac;
                uint32_t bhi[2], blo[2];
                bhi[0] = *(const uint32_t*)(sb + OFF_WHI + bbase);
                bhi[1] = *(const uint32_t*)(sb + OFF_WHI + bbase + 16);
                blo[0] = *(const uint32_t*)(sb + OFF_WLO + bbase);
                blo[1] = *(const uint32_t*)(sb + OFF_WLO + bbase + 16);
                #pragma unroll
                for (int mt = 0; mt < 2; ++mt) {
                    mma16816(acc[mt][nt], ahi[mt], bhi);
                    mma16816(acc[mt][nt], ahi[mt], blo);
                    mma16816(acc[mt][nt], alo[mt], bhi);
                }
            }
        }

        // ---- epilogue: acc + bias -> global fp32 ----
        const float* bp = bias[m];
        float* og = outm[m];
        #pragma unroll
        for (int mt = 0; mt < 2; ++mt) {
            int grow = row0 + mw * 32 + mt * 16 + ar;
            #pragma unroll
            for (int nt = 0; nt < 4; ++nt) {
                int c = nw * 32 + nt * 8 + ((lane & 3) << 1);
                float2 b2 = *(const float2*)(bp + c);
                float2 lo = make_float2(acc[mt][nt][0] + b2.x,
                                        acc[mt][nt][1] + b2.y);
                float2 hi = make_float2(acc[mt][nt][2] + b2.x,
                                        acc[mt][nt][3] + b2.y);
                *(float2*)(og + (size_t)grow * DD + c)       = lo;
                *(float2*)(og + (size_t)(grow + 8) * DD + c) = hi;
            }
        }
    }
}

// ===================== attention (unchanged from R3) =====================

__device__ __forceinline__ int swz(int r, int d4) {
    return r * DD + (((d4 ^ r) & 31) << 2);
}

#define DOT4A(A, QV, KV) \
    A = fmaf(QV.x, KV.x, A); A = fmaf(QV.y, KV.y, A); \
    A = fmaf(QV.z, KV.z, A); A = fmaf(QV.w, KV.w, A);

#define OUT_FMA(A, P, VV) \
    A.x = fmaf(P, VV.x, A.x); A.y = fmaf(P, VV.y, A.y); \
    A.z = fmaf(P, VV.z, A.z); A.w = fmaf(P, VV.w, A.w);

__global__ void __launch_bounds__(256, 2) attn_kernel(float* __restrict__ outp)
{
    extern __shared__ float sm[];
    float* ks    = sm;
    float* qs    = sm + KROWS * DD;
    float* probs = sm + KROWS * DD;

    const int tid  = threadIdx.x;
    const int wid  = tid >> 5;
    const int lane = tid & 31;
    const int blk  = blockIdx.x;
    const int b    = blk >> 7;
    const int s0   = (blk & 127) * TQ;
    const int lo   = s0 - HALF;

    const float* kg = g_k + (size_t)b * SS * DD;
    const float* vg = g_v + (size_t)b * SS * DD;
    const float* qg = g_q + (size_t)b * SS * DD;

    for (int idx = tid; idx < KROWS * 32; idx += 256) {
        int r = idx >> 5, d4 = idx & 31;
        int g = lo + r;
        float4 kv = make_float4(0.f, 0.f, 0.f, 0.f);
        if ((unsigned)g < SS)
            kv = *(const float4*)(kg + (size_t)g * DD + (d4 << 2));
        *(float4*)(ks + swz(r, d4)) = kv;
    }
    {
        const float4* src = (const float4*)(qg + (size_t)s0 * DD);
        float4* dst = (float4*)qs;
        for (int i = tid; i < TQ * 32; i += 256) dst[i] = src[i];
    }
    __syncthreads();

    const int iqw = wid << 2;
    float acc[5][4];
    #pragma unroll
    for (int t = 0; t < 5; ++t)
        #pragma unroll
        for (int qi = 0; qi < 4; ++qi) acc[t][qi] = 0.f;

    const float* q0p = qs + (iqw + 0) * DD;
    const float* q1p = qs + (iqw + 1) * DD;
    const float* q2p = qs + (iqw + 2) * DD;
    const float* q3p = qs + (iqw + 3) * DD;

    #pragma unroll 4
    for (int d4 = 0; d4 < 32; ++d4) {
        float4 q0 = *(const float4*)(q0p + (d4 << 2));
        float4 q1 = *(const float4*)(q1p + (d4 << 2));
        float4 q2 = *(const float4*)(q2p + (d4 << 2));
        float4 q3 = *(const float4*)(q3p + (d4 << 2));
        #pragma unroll
        for (int t = 0; t < 5; ++t) {
            float4 kv = *(const float4*)(ks + swz(t * 32 + lane, d4));
            DOT4A(acc[t][0], q0, kv);
            DOT4A(acc[t][1], q1, kv);
            DOT4A(acc[t][2], q2, kv);
            DOT4A(acc[t][3], q3, kv);
        }
    }

    const float scale = 0.08838834764831844f;
    float wsum[4];
    #pragma unroll
    for (int qi = 0; qi < 4; ++qi) {
        int iq = iqw + qi;
        float mm = -INFINITY;
        #pragma unroll
        for (int t = 0; t < 5; ++t) {
            int r = t * 32 + lane;
            int j = r - iq;
            int g = lo + r;
            bool valid = (j >= 0) && (j <= 128) && ((unsigned)g < SS);
            acc[t][qi] = valid ? acc[t][qi] * scale : NEG_INF_F;
            mm = fmaxf(mm, acc[t][qi]);
        }
        mm = fmaxf(mm, __shfl_xor_sync(0xffffffffu, mm, 1));
        mm = fmaxf(mm, __shfl_xor_sync(0xffffffffu, mm, 2));
        mm = fmaxf(mm, __shfl_xor_sync(0xffffffffu, mm, 4));
        mm = fmaxf(mm, __shfl_xor_sync(0xffffffffu, mm, 8));
        mm = fmaxf(mm, __shfl_xor_sync(0xffffffffu, mm, 16));
        float s = 0.f;
        #pragma unroll
        for (int t = 0; t < 5; ++t) {
            float e = __expf(acc[t][qi] - mm);
            acc[t][qi] = e;
            s += e;
        }
        s += __shfl_xor_sync(0xffffffffu, s, 1);
        s += __shfl_xor_sync(0xffffffffu, s, 2);
        s += __shfl_xor_sync(0xffffffffu, s, 4);
        s += __shfl_xor_sync(0xffffffffu, s, 8);
        s += __shfl_xor_sync(0xffffffffu, s, 16);
        wsum[qi] = s;
    }

    __syncthreads();

    float* pw = probs + wid * PWARP;
    for (int i = lane; i < PWARP; i += 32) pw[i] = 0.f;
    __syncwarp();
    #pragma unroll
    for (int qi = 0; qi < 4; ++qi) {
        int iq = iqw + qi;
        #pragma unroll
        for (int t = 0; t < 5; ++t) {
            int j = t * 32 + lane - iq;
            if (j >= -4 && j <= 131)
                pw[qi * PW + 4 + j] = acc[t][qi];
        }
    }
    __syncwarp();

    {
        float4 o0 = make_float4(0,0,0,0), o1 = o0, o2 = o0, o3 = o0;
        const float* p0b = pw + 0 * PW + 4;
        const float* p1b = pw + 1 * PW + 3;
        const float* p2b = pw + 2 * PW + 2;
        const float* p3b = pw + 3 * PW + 1;
        #pragma unroll 4
        for (int rr = 0; rr < 132; ++rr) {
            int g = lo + iqw + rr;
            int gc = min(max(g, 0), SS - 1);
            float4 vv = __ldg((const float4*)(vg + (size_t)gc * DD + (lane << 2)));
            float p0 = p0b[rr];
            float p1 = p1b[rr];
            float p2 = p2b[rr];
            float p3 = p3b[rr];
            OUT_FMA(o0, p0, vv);
            OUT_FMA(o1, p1, vv);
            OUT_FMA(o2, p2, vv);
            OUT_FMA(o3, p3, vv);
        }
        float inv0 = 1.0f / wsum[0];
        float inv1 = 1.0f / wsum[1];
        float inv2 = 1.0f / wsum[2];
        float inv3 = 1.0f / wsum[3];
        float* op = outp + ((size_t)b * SS + s0 + iqw) * DD + (lane << 2);
        *(float4*)(op + 0 * DD) = make_float4(o0.x*inv0, o0.y*inv0, o0.z*inv0, o0.w*inv0);
        *(float4*)(op + 1 * DD) = make_float4(o1.x*inv1, o1.y*inv1, o1.z*inv1, o1.w*inv1);
        *(float4*)(op + 2 * DD) = make_float4(o2.x*inv2, o2.y*inv2, o2.z*inv2, o2.w*inv2);
        *(float4*)(op + 3 * DD) = make_float4(o3.x*inv3, o3.y*inv3, o3.z*inv3, o3.w*inv3);
    }
}

extern "C" void kernel_launch(void* const* d_in, const int* in_sizes, int n_in,
                              void* d_out, int out_size)
{
    const float* x  = (const float*)d_in[0];
    const float* Wq = (const float*)d_in[1];
    const float* bq = (const float*)d_in[2];
    const float* Wk = (const float*)d_in[3];
    const float* bk = (const float*)d_in[4];
    const float* Wv = (const float*)d_in[5];
    const float* bv = (const float*)d_in[6];
    float* out = (float*)d_out;

    cudaFuncSetAttribute(qkv_mma_kernel,
                         cudaFuncAttributeMaxDynamicSharedMemorySize, QKV_SMEM);
    const int union_floats = (8 * PWARP > TQ * DD) ? 8 * PWARP : TQ * DD;
    const int attn_smem = (KROWS * DD + union_floats) * (int)sizeof(float);
    cudaFuncSetAttribute(attn_kernel,
                         cudaFuncAttributeMaxDynamicSharedMemorySize, attn_smem);

    qkv_mma_kernel<<<BB * SS / 64, 256, QKV_SMEM>>>(x, Wq, bq, Wk, bk, Wv, bv);
    attn_kernel<<<BB * SS / TQ, 256, attn_smem>>>(out);
}

// round 6
// speedup vs baseline: 1.1950x; 1.1950x over previous
#include <cuda_runtime.h>
#include <cuda_bf16.h>
#include <math.h>
#include <stdint.h>

#define BB 2
#define SS 4096
#define DD 128
#define HALF 64
#define TQ 32
#define KROWS (TQ + 2*HALF)   /* 160 */
#define PW 136
#define PWARP (4*PW)
#define NEG_INF_F (-1e30f)

__device__ float g_q[BB*SS*DD];
__device__ float g_k[BB*SS*DD];
__device__ float g_v[BB*SS*DD];

#define S136 136               /* bf16 elems per smem/global W row */

// Pre-converted, pre-transposed W: Wt[n][k] as bf16 hi/lo, row stride S136.
__device__ __nv_bfloat16 g_wt_hi[3][128*S136];
__device__ __nv_bfloat16 g_wt_lo[3][128*S136];

// ===================== one-shot W convert/transpose =====================

__global__ void __launch_bounds__(256) wconv_kernel(
    const float* __restrict__ Wq, const float* __restrict__ Wk,
    const float* __restrict__ Wv)
{
    const float* Wm[3] = {Wq, Wk, Wv};
    const float* Wg = Wm[blockIdx.x];
    __nv_bfloat16* whi = g_wt_hi[blockIdx.x];
    __nv_bfloat16* wlo = g_wt_lo[blockIdx.x];
    __shared__ float ts[32][33];
    const int tid = threadIdx.x;

    for (int t = 0; t < 16; ++t) {
        int tr = t >> 2, tc = t & 3;      // tr: k block, tc: n block
        __syncthreads();
        #pragma unroll
        for (int e = 0; e < 4; ++e) {
            int li = tid + e * 256;
            int r = li >> 5, c = li & 31;
            ts[r][c] = Wg[(size_t)(tr * 32 + r) * DD + tc * 32 + c];  // coalesced
        }
        __syncthreads();
        #pragma unroll
        for (int e = 0; e < 4; ++e) {
            int li = tid + e * 256;
            int n = li >> 5, k = li & 31;
            float v = ts[k][n];
            __nv_bfloat16 h = __float2bfloat16(v);
            int o = (tc * 32 + n) * S136 + tr * 32 + k;               // coalesced
            whi[o] = h;
            wlo[o] = __float2bfloat16(v - __bfloat162float(h));
        }
    }
}

// ===================== QKV via mma.sync bf16 =====================
// 128 CTAs x 64 rows. D = x_hi@W_hi + x_hi@W_lo + x_lo@W_hi (Dekker split).

#define XTILE_B (64  * S136 * 2)       /* 17408 */
#define WTILE_B (128 * S136 * 2)       /* 34816 */
#define OFF_XHI 0
#define OFF_XLO (OFF_XHI + XTILE_B)
#define OFF_WHI (OFF_XLO + XTILE_B)
#define OFF_WLO (OFF_WHI + WTILE_B)
#define QKV_SMEM (OFF_WLO + WTILE_B)   /* 104448 */

__device__ __forceinline__ void mma16816(float* d, const uint32_t* a,
                                         const uint32_t* b) {
    asm volatile(
        "mma.sync.aligned.m16n8k16.row.col.f32.bf16.bf16.f32 "
        "{%0,%1,%2,%3}, {%4,%5,%6,%7}, {%8,%9}, {%0,%1,%2,%3};\n"
        : "+f"(d[0]), "+f"(d[1]), "+f"(d[2]), "+f"(d[3])
        : "r"(a[0]), "r"(a[1]), "r"(a[2]), "r"(a[3]), "r"(b[0]), "r"(b[1]));
}

__device__ __forceinline__ __nv_bfloat162 split_hi2(float x, float y) {
    return __nv_bfloat162(__float2bfloat16(x), __float2bfloat16(y));
}
__device__ __forceinline__ __nv_bfloat162 split_lo2(float x, float y) {
    float hx = __bfloat162float(__float2bfloat16(x));
    float hy = __bfloat162float(__float2bfloat16(y));
    return __nv_bfloat162(__float2bfloat16(x - hx), __float2bfloat16(y - hy));
}

__global__ void __launch_bounds__(256) qkv_mma_kernel(
    const float* __restrict__ x,
    const float* __restrict__ bq, const float* __restrict__ bk,
    const float* __restrict__ bv)
{
    extern __shared__ char sb[];
    const int tid  = threadIdx.x;
    const int wid  = tid >> 5;
    const int lane = tid & 31;
    const int row0 = blockIdx.x * 64;

    // ---- convert x tile: 64x128 fp32 -> hi/lo bf16, row stride S136 ----
    for (int idx = tid; idx < 64 * 64; idx += 256) {
        int r = idx >> 6, k = (idx & 63) << 1;
        float2 v = *(const float2*)(x + (size_t)(row0 + r) * DD + k);
        int off = (r * S136 + k) * 2;
        *(__nv_bfloat162*)(sb + OFF_XHI + off) = split_hi2(v.x, v.y);
        *(__nv_bfloat162*)(sb + OFF_XLO + off) = split_lo2(v.x, v.y);
    }

    const float* bias[3] = {bq, bk, bv};
    float* outm[3];
    outm[0] = g_q; outm[1] = g_k; outm[2] = g_v;

    const int mw = wid & 1;          // M group (32 rows)
    const int nw = wid >> 1;         // N group (32 cols)
    const int ar = lane >> 2;        // fragment row within 8
    const int ac = (lane & 3) << 2;  // fragment byte col offset

    for (int m = 0; m < 3; ++m) {
        if (m > 0) __syncthreads();  // prior matrix's mma reads done

        // ---- copy pre-converted W image into smem (pure uint4 memcpy) ----
        {
            const uint4* shi = (const uint4*)g_wt_hi[m];
            const uint4* slo = (const uint4*)g_wt_lo[m];
            uint4* dhi = (uint4*)(sb + OFF_WHI);
            uint4* dlo = (uint4*)(sb + OFF_WLO);
            for (int i = tid; i < WTILE_B / 16; i += 256) {
                dhi[i] = shi[i];
                dlo[i] = slo[i];
            }
        }
        __syncthreads();

        // ---- mma mainloop: warp tile M32 x N32, K=128 in 8 steps ----
        float acc[2][4][4];
        #pragma unroll
        for (int mt = 0; mt < 2; ++mt)
            #pragma unroll
            for (int nt = 0; nt < 4; ++nt)
                #pragma unroll
                for (int e = 0; e < 4; ++e) acc[mt][nt][e] = 0.f;

        #pragma unroll
        for (int ks = 0; ks < 8; ++ks) {
            const int kb = ks * 32;
            uint32_t ahi[2][4], alo[2][4];
            #pragma unroll
            for (int mt = 0; mt < 2; ++mt) {
                int abase = (mw * 32 + mt * 16 + ar) * 272 + kb + ac;
                ahi[mt][0] = *(const uint32_t*)(sb + OFF_XHI + abase);
                ahi[mt][1] = *(const uint32_t*)(sb + OFF_XHI + abase + 8*272);
                ahi[mt][2] = *(const uint32_t*)(sb + OFF_XHI + abase + 16);
                ahi[mt][3] = *(const uint32_t*)(sb + OFF_XHI + abase + 8*272 + 16);
                alo[mt][0] = *(const uint32_t*)(sb + OFF_XLO + abase);
                alo[mt][1] = *(const uint32_t*)(sb + OFF_XLO + abase + 8*272);
                alo[mt][2] = *(const uint32_t*)(sb + OFF_XLO + abase + 16);
                alo[mt][3] = *(const uint32_t*)(sb + OFF_XLO + abase + 8*272 + 16);
            }
            #pragma unroll
            for (int nt = 0; nt < 4; ++nt) {
                int bbase = (nw * 32 + nt * 8 + ar) * 272 + kb + ac;
                uint32_t bhi[2], blo[2];
                bhi[0] = *(const uint32_t*)(sb + OFF_WHI + bbase);
                bhi[1] = *(const uint32_t*)(sb + OFF_WHI + bbase + 16);
                blo[0] = *(const uint32_t*)(sb + OFF_WLO + bbase);
                blo[1] = *(const uint32_t*)(sb + OFF_WLO + bbase + 16);
                #pragma unroll
                for (int mt = 0; mt < 2; ++mt) {
                    mma16816(acc[mt][nt], ahi[mt], bhi);
                    mma16816(acc[mt][nt], ahi[mt], blo);
                    mma16816(acc[mt][nt], alo[mt], bhi);
                }
            }
        }

        // ---- epilogue: acc + bias -> global fp32 ----
        const float* bp = bias[m];
        float* og = outm[m];
        #pragma unroll
        for (int mt = 0; mt < 2; ++mt) {
            int grow = row0 + mw * 32 + mt * 16 + ar;
            #pragma unroll
            for (int nt = 0; nt < 4; ++nt) {
                int c = nw * 32 + nt * 8 + ((lane & 3) << 1);
                float2 b2 = *(const float2*)(bp + c);
                float2 lo = make_float2(acc[mt][nt][0] + b2.x,
                                        acc[mt][nt][1] + b2.y);
                float2 hi = make_float2(acc[mt][nt][2] + b2.x,
                                        acc[mt][nt][3] + b2.y);
                *(float2*)(og + (size_t)grow * DD + c)       = lo;
                *(float2*)(og + (size_t)(grow + 8) * DD + c) = hi;
            }
        }
    }
}

// ===================== attention (unchanged from R3) =====================

__device__ __forceinline__ int swz(int r, int d4) {
    return r * DD + (((d4 ^ r) & 31) << 2);
}

#define DOT4A(A, QV, KV) \
    A = fmaf(QV.x, KV.x, A); A = fmaf(QV.y, KV.y, A); \
    A = fmaf(QV.z, KV.z, A); A = fmaf(QV.w, KV.w, A);

#define OUT_FMA(A, P, VV) \
    A.x = fmaf(P, VV.x, A.x); A.y = fmaf(P, VV.y, A.y); \
    A.z = fmaf(P, VV.z, A.z); A.w = fmaf(P, VV.w, A.w);

__global__ void __launch_bounds__(256, 2) attn_kernel(float* __restrict__ outp)
{
    extern __shared__ float sm[];
    float* ks    = sm;
    float* qs    = sm + KROWS * DD;
    float* probs = sm + KROWS * DD;

    const int tid  = threadIdx.x;
    const int wid  = tid >> 5;
    const int lane = tid & 31;
    const int blk  = blockIdx.x;
    const int b    = blk >> 7;
    const int s0   = (blk & 127) * TQ;
    const int lo   = s0 - HALF;

    const float* kg = g_k + (size_t)b * SS * DD;
    const float* vg = g_v + (size_t)b * SS * DD;
    const float* qg = g_q + (size_t)b * SS * DD;

    for (int idx = tid; idx < KROWS * 32; idx += 256) {
        int r = idx >> 5, d4 = idx & 31;
        int g = lo + r;
        float4 kv = make_float4(0.f, 0.f, 0.f, 0.f);
        if ((unsigned)g < SS)
            kv = *(const float4*)(kg + (size_t)g * DD + (d4 << 2));
        *(float4*)(ks + swz(r, d4)) = kv;
    }
    {
        const float4* src = (const float4*)(qg + (size_t)s0 * DD);
        float4* dst = (float4*)qs;
        for (int i = tid; i < TQ * 32; i += 256) dst[i] = src[i];
    }
    __syncthreads();

    const int iqw = wid << 2;
    float acc[5][4];
    #pragma unroll
    for (int t = 0; t < 5; ++t)
        #pragma unroll
        for (int qi = 0; qi < 4; ++qi) acc[t][qi] = 0.f;

    const float* q0p = qs + (iqw + 0) * DD;
    const float* q1p = qs + (iqw + 1) * DD;
    const float* q2p = qs + (iqw + 2) * DD;
    const float* q3p = qs + (iqw + 3) * DD;

    #pragma unroll 4
    for (int d4 = 0; d4 < 32; ++d4) {
        float4 q0 = *(const float4*)(q0p + (d4 << 2));
        float4 q1 = *(const float4*)(q1p + (d4 << 2));
        float4 q2 = *(const float4*)(q2p + (d4 << 2));
        float4 q3 = *(const float4*)(q3p + (d4 << 2));
        #pragma unroll
        for (int t = 0; t < 5; ++t) {
            float4 kv = *(const float4*)(ks + swz(t * 32 + lane, d4));
            DOT4A(acc[t][0], q0, kv);
            DOT4A(acc[t][1], q1, kv);
            DOT4A(acc[t][2], q2, kv);
            DOT4A(acc[t][3], q3, kv);
        }
    }

    const float scale = 0.08838834764831844f;
    float wsum[4];
    #pragma unroll
    for (int qi = 0; qi < 4; ++qi) {
        int iq = iqw + qi;
        float mm = -INFINITY;
        #pragma unroll
        for (int t = 0; t < 5; ++t) {
            int r = t * 32 + lane;
            int j = r - iq;
            int g = lo + r;
            bool valid = (j >= 0) && (j <= 128) && ((unsigned)g < SS);
            acc[t][qi] = valid ? acc[t][qi] * scale : NEG_INF_F;
            mm = fmaxf(mm, acc[t][qi]);
        }
        mm = fmaxf(mm, __shfl_xor_sync(0xffffffffu, mm, 1));
        mm = fmaxf(mm, __shfl_xor_sync(0xffffffffu, mm, 2));
        mm = fmaxf(mm, __shfl_xor_sync(0xffffffffu, mm, 4));
        mm = fmaxf(mm, __shfl_xor_sync(0xffffffffu, mm, 8));
        mm = fmaxf(mm, __shfl_xor_sync(0xffffffffu, mm, 16));
        float s = 0.f;
        #pragma unroll
        for (int t = 0; t < 5; ++t) {
            float e = __expf(acc[t][qi] - mm);
            acc[t][qi] = e;
            s += e;
        }
        s += __shfl_xor_sync(0xffffffffu, s, 1);
        s += __shfl_xor_sync(0xffffffffu, s, 2);
        s += __shfl_xor_sync(0xffffffffu, s, 4);
        s += __shfl_xor_sync(0xffffffffu, s, 8);
        s += __shfl_xor_sync(0xffffffffu, s, 16);
        wsum[qi] = s;
    }

    __syncthreads();

    float* pw = probs + wid * PWARP;
    for (int i = lane; i < PWARP; i += 32) pw[i] = 0.f;
    __syncwarp();
    #pragma unroll
    for (int qi = 0; qi < 4; ++qi) {
        int iq = iqw + qi;
        #pragma unroll
        for (int t = 0; t < 5; ++t) {
            int j = t * 32 + lane - iq;
            if (j >= -4 && j <= 131)
                pw[qi * PW + 4 + j] = acc[t][qi];
        }
    }
    __syncwarp();

    {
        float4 o0 = make_float4(0,0,0,0), o1 = o0, o2 = o0, o3 = o0;
        const float* p0b = pw + 0 * PW + 4;
        const float* p1b = pw + 1 * PW + 3;
        const float* p2b = pw + 2 * PW + 2;
        const float* p3b = pw + 3 * PW + 1;
        #pragma unroll 4
        for (int rr = 0; rr < 132; ++rr) {
            int g = lo + iqw + rr;
            int gc = min(max(g, 0), SS - 1);
            float4 vv = __ldg((const float4*)(vg + (size_t)gc * DD + (lane << 2)));
            float p0 = p0b[rr];
            float p1 = p1b[rr];
            float p2 = p2b[rr];
            float p3 = p3b[rr];
            OUT_FMA(o0, p0, vv);
            OUT_FMA(o1, p1, vv);
            OUT_FMA(o2, p2, vv);
            OUT_FMA(o3, p3, vv);
        }
        float inv0 = 1.0f / wsum[0];
        float inv1 = 1.0f / wsum[1];
        float inv2 = 1.0f / wsum[2];
        float inv3 = 1.0f / wsum[3];
        float* op = outp + ((size_t)b * SS + s0 + iqw) * DD + (lane << 2);
        *(float4*)(op + 0 * DD) = make_float4(o0.x*inv0, o0.y*inv0, o0.z*inv0, o0.w*inv0);
        *(float4*)(op + 1 * DD) = make_float4(o1.x*inv1, o1.y*inv1, o1.z*inv1, o1.w*inv1);
        *(float4*)(op + 2 * DD) = make_float4(o2.x*inv2, o2.y*inv2, o2.z*inv2, o2.w*inv2);
        *(float4*)(op + 3 * DD) = make_float4(o3.x*inv3, o3.y*inv3, o3.z*inv3, o3.w*inv3);
    }
}

extern "C" void kernel_launch(void* const* d_in, const int* in_sizes, int n_in,
                              void* d_out, int out_size)
{
    const float* x  = (const float*)d_in[0];
    const float* Wq = (const float*)d_in[1];
    const float* bq = (const float*)d_in[2];
    const float* Wk = (const float*)d_in[3];
    const float* bk = (const float*)d_in[4];
    const float* Wv = (const float*)d_in[5];
    const float* bv = (const float*)d_in[6];
    float* out = (float*)d_out;

    cudaFuncSetAttribute(qkv_mma_kernel,
                         cudaFuncAttributeMaxDynamicSharedMemorySize, QKV_SMEM);
    const int union_floats = (8 * PWARP > TQ * DD) ? 8 * PWARP : TQ * DD;
    const int attn_smem = (KROWS * DD + union_floats) * (int)sizeof(float);
    cudaFuncSetAttribute(attn_kernel,
                         cudaFuncAttributeMaxDynamicSharedMemorySize, attn_smem);

    wconv_kernel<<<3, 256>>>(Wq, Wk, Wv);
    qkv_mma_kernel<<<BB * SS / 64, 256, QKV_SMEM>>>(x, bq, bk, bv);
    attn_kernel<<<BB * SS / TQ, 256, attn_smem>>>(out);
}

// round 7
// speedup vs baseline: 1.4528x; 1.2157x over previous
#include <cuda_runtime.h>
#include <cuda_bf16.h>
#include <math.h>
#include <stdint.h>

#define BB 2
#define SS 4096
#define DD 128
#define HALF 64
#define TQ 32
#define KROWS (TQ + 2*HALF)   /* 160 */
#define PW 136
#define PWARP (4*PW)
#define NEG_INF_F (-1e30f)

__device__ float g_q[BB*SS*DD];
__device__ float g_k[BB*SS*DD];
__device__ float g_v[BB*SS*DD];

#define S136 136               /* bf16 elems per smem/global W row */

// Pre-converted, pre-transposed W: Wt[n][k] as bf16 hi/lo, row stride S136.
__device__ __nv_bfloat16 g_wt_hi[3][128*S136];
__device__ __nv_bfloat16 g_wt_lo[3][128*S136];

// ============ one-shot W convert/transpose: 48 CTAs, one tile each ============

__global__ void __launch_bounds__(256) wconv_kernel(
    const float* __restrict__ Wq, const float* __restrict__ Wk,
    const float* __restrict__ Wv)
{
    const float* Wm[3] = {Wq, Wk, Wv};
    const float* Wg = Wm[blockIdx.x];
    __nv_bfloat16* whi = g_wt_hi[blockIdx.x];
    __nv_bfloat16* wlo = g_wt_lo[blockIdx.x];
    __shared__ float ts[32][33];
    const int tid = threadIdx.x;
    const int t   = blockIdx.y;       // 0..15
    const int tr  = t >> 2;           // k block
    const int tc  = t & 3;            // n block

    #pragma unroll
    for (int e = 0; e < 4; ++e) {
        int li = tid + e * 256;
        int r = li >> 5, c = li & 31;
        ts[r][c] = Wg[(size_t)(tr * 32 + r) * DD + tc * 32 + c];  // coalesced
    }
    __syncthreads();
    #pragma unroll
    for (int e = 0; e < 4; ++e) {
        int li = tid + e * 256;
        int n = li >> 5, k = li & 31;
        float v = ts[k][n];
        __nv_bfloat16 h = __float2bfloat16(v);
        int o = (tc * 32 + n) * S136 + tr * 32 + k;               // coalesced
        whi[o] = h;
        wlo[o] = __float2bfloat16(v - __bfloat162float(h));
    }
}

// ===================== QKV via mma.sync bf16 =====================
// 128 CTAs x 64 rows. D = x_hi@W_hi + x_hi@W_lo + x_lo@W_hi (Dekker split).

#define XTILE_B (64  * S136 * 2)       /* 17408 */
#define WTILE_B (128 * S136 * 2)       /* 34816 */
#define OFF_XHI 0
#define OFF_XLO (OFF_XHI + XTILE_B)
#define OFF_WHI (OFF_XLO + XTILE_B)
#define OFF_WLO (OFF_WHI + WTILE_B)
#define QKV_SMEM (OFF_WLO + WTILE_B)   /* 104448 */

__device__ __forceinline__ void mma16816(float* d, const uint32_t* a,
                                         const uint32_t* b) {
    asm volatile(
        "mma.sync.aligned.m16n8k16.row.col.f32.bf16.bf16.f32 "
        "{%0,%1,%2,%3}, {%4,%5,%6,%7}, {%8,%9}, {%0,%1,%2,%3};\n"
        : "+f"(d[0]), "+f"(d[1]), "+f"(d[2]), "+f"(d[3])
        : "r"(a[0]), "r"(a[1]), "r"(a[2]), "r"(a[3]), "r"(b[0]), "r"(b[1]));
}

__device__ __forceinline__ __nv_bfloat162 split_hi2(float x, float y) {
    return __nv_bfloat162(__float2bfloat16(x), __float2bfloat16(y));
}
__device__ __forceinline__ __nv_bfloat162 split_lo2(float x, float y) {
    float hx = __bfloat162float(__float2bfloat16(x));
    float hy = __bfloat162float(__float2bfloat16(y));
    return __nv_bfloat162(__float2bfloat16(x - hx), __float2bfloat16(y - hy));
}

__global__ void __launch_bounds__(256) qkv_mma_kernel(
    const float* __restrict__ x,
    const float* __restrict__ bq, const float* __restrict__ bk,
    const float* __restrict__ bv)
{
    extern __shared__ char sb[];
    const int tid  = threadIdx.x;
    const int wid  = tid >> 5;
    const int lane = tid & 31;
    const int row0 = blockIdx.x * 64;

    // ---- convert x tile: 64x128 fp32 -> hi/lo bf16, row stride S136 ----
    for (int idx = tid; idx < 64 * 64; idx += 256) {
        int r = idx >> 6, k = (idx & 63) << 1;
        float2 v = *(const float2*)(x + (size_t)(row0 + r) * DD + k);
        int off = (r * S136 + k) * 2;
        *(__nv_bfloat162*)(sb + OFF_XHI + off) = split_hi2(v.x, v.y);
        *(__nv_bfloat162*)(sb + OFF_XLO + off) = split_lo2(v.x, v.y);
    }

    const float* bias[3] = {bq, bk, bv};
    float* outm[3];
    outm[0] = g_q; outm[1] = g_k; outm[2] = g_v;

    const int mw = wid & 1;          // M group (32 rows)
    const int nw = wid >> 1;         // N group (32 cols)
    const int ar = lane >> 2;        // fragment row within 8
    const int ac = (lane & 3) << 2;  // fragment byte col offset

    for (int m = 0; m < 3; ++m) {
        if (m > 0) __syncthreads();  // prior matrix's mma reads done

        // ---- copy pre-converted W image into smem (pure uint4 memcpy) ----
        {
            const uint4* shi = (const uint4*)g_wt_hi[m];
            const uint4* slo = (const uint4*)g_wt_lo[m];
            uint4* dhi = (uint4*)(sb + OFF_WHI);
            uint4* dlo = (uint4*)(sb + OFF_WLO);
            for (int i = tid; i < WTILE_B / 16; i += 256) {
                dhi[i] = shi[i];
                dlo[i] = slo[i];
            }
        }
        __syncthreads();

        // ---- mma mainloop: warp tile M32 x N32, K=128 in 8 steps ----
        float acc[2][4][4];
        #pragma unroll
        for (int mt = 0; mt < 2; ++mt)
            #pragma unroll
            for (int nt = 0; nt < 4; ++nt)
                #pragma unroll
                for (int e = 0; e < 4; ++e) acc[mt][nt][e] = 0.f;

        #pragma unroll
        for (int ks = 0; ks < 8; ++ks) {
            const int kb = ks * 32;
            uint32_t ahi[2][4], alo[2][4];
            #pragma unroll
            for (int mt = 0; mt < 2; ++mt) {
                int abase = (mw * 32 + mt * 16 + ar) * 272 + kb + ac;
                ahi[mt][0] = *(const uint32_t*)(sb + OFF_XHI + abase);
                ahi[mt][1] = *(const uint32_t*)(sb + OFF_XHI + abase + 8*272);
                ahi[mt][2] = *(const uint32_t*)(sb + OFF_XHI + abase + 16);
                ahi[mt][3] = *(const uint32_t*)(sb + OFF_XHI + abase + 8*272 + 16);
                alo[mt][0] = *(const uint32_t*)(sb + OFF_XLO + abase);
                alo[mt][1] = *(const uint32_t*)(sb + OFF_XLO + abase + 8*272);
                alo[mt][2] = *(const uint32_t*)(sb + OFF_XLO + abase + 16);
                alo[mt][3] = *(const uint32_t*)(sb + OFF_XLO + abase + 8*272 + 16);
            }
            #pragma unroll
            for (int nt = 0; nt < 4; ++nt) {
                int bbase = (nw * 32 + nt * 8 + ar) * 272 + kb + ac;
                uint32_t bhi[2], blo[2];
                bhi[0] = *(const uint32_t*)(sb + OFF_WHI + bbase);
                bhi[1] = *(const uint32_t*)(sb + OFF_WHI + bbase + 16);
                blo[0] = *(const uint32_t*)(sb + OFF_WLO + bbase);
                blo[1] = *(const uint32_t*)(sb + OFF_WLO + bbase + 16);
                #pragma unroll
                for (int mt = 0; mt < 2; ++mt) {
                    mma16816(acc[mt][nt], ahi[mt], bhi);
                    mma16816(acc[mt][nt], ahi[mt], blo);
                    mma16816(acc[mt][nt], alo[mt], bhi);
                }
            }
        }

        // ---- epilogue: acc + bias -> global fp32 ----
        const float* bp = bias[m];
        float* og = outm[m];
        #pragma unroll
        for (int mt = 0; mt < 2; ++mt) {
            int grow = row0 + mw * 32 + mt * 16 + ar;
            #pragma unroll
            for (int nt = 0; nt < 4; ++nt) {
                int c = nw * 32 + nt * 8 + ((lane & 3) << 1);
                float2 b2 = *(const float2*)(bp + c);
                float2 lo = make_float2(acc[mt][nt][0] + b2.x,
                                        acc[mt][nt][1] + b2.y);
                float2 hi = make_float2(acc[mt][nt][2] + b2.x,
                                        acc[mt][nt][3] + b2.y);
                *(float2*)(og + (size_t)grow * DD + c)       = lo;
                *(float2*)(og + (size_t)(grow + 8) * DD + c) = hi;
            }
        }
    }
}

// ===================== attention (unchanged from R3) =====================

__device__ __forceinline__ int swz(int r, int d4) {
    return r * DD + (((d4 ^ r) & 31) << 2);
}

#define DOT4A(A, QV, KV) \
    A = fmaf(QV.x, KV.x, A); A = fmaf(QV.y, KV.y, A); \
    A = fmaf(QV.z, KV.z, A); A = fmaf(QV.w, KV.w, A);

#define OUT_FMA(A, P, VV) \
    A.x = fmaf(P, VV.x, A.x); A.y = fmaf(P, VV.y, A.y); \
    A.z = fmaf(P, VV.z, A.z); A.w = fmaf(P, VV.w, A.w);

__global__ void __launch_bounds__(256, 2) attn_kernel(float* __restrict__ outp)
{
    extern __shared__ float sm[];
    float* ks    = sm;
    float* qs    = sm + KROWS * DD;
    float* probs = sm + KROWS * DD;

    const int tid  = threadIdx.x;
    const int wid  = tid >> 5;
    const int lane = tid & 31;
    const int blk  = blockIdx.x;
    const int b    = blk >> 7;
    const int s0   = (blk & 127) * TQ;
    const int lo   = s0 - HALF;

    const float* kg = g_k + (size_t)b * SS * DD;
    const float* vg = g_v + (size_t)b * SS * DD;
    const float* qg = g_q + (size_t)b * SS * DD;

    for (int idx = tid; idx < KROWS * 32; idx += 256) {
        int r = idx >> 5, d4 = idx & 31;
        int g = lo + r;
        float4 kv = make_float4(0.f, 0.f, 0.f, 0.f);
        if ((unsigned)g < SS)
            kv = *(const float4*)(kg + (size_t)g * DD + (d4 << 2));
        *(float4*)(ks + swz(r, d4)) = kv;
    }
    {
        const float4* src = (const float4*)(qg + (size_t)s0 * DD);
        float4* dst = (float4*)qs;
        for (int i = tid; i < TQ * 32; i += 256) dst[i] = src[i];
    }
    __syncthreads();

    const int iqw = wid << 2;
    float acc[5][4];
    #pragma unroll
    for (int t = 0; t < 5; ++t)
        #pragma unroll
        for (int qi = 0; qi < 4; ++qi) acc[t][qi] = 0.f;

    const float* q0p = qs + (iqw + 0) * DD;
    const float* q1p = qs + (iqw + 1) * DD;
    const float* q2p = qs + (iqw + 2) * DD;
    const float* q3p = qs + (iqw + 3) * DD;

    #pragma unroll 4
    for (int d4 = 0; d4 < 32; ++d4) {
        float4 q0 = *(const float4*)(q0p + (d4 << 2));
        float4 q1 = *(const float4*)(q1p + (d4 << 2));
        float4 q2 = *(const float4*)(q2p + (d4 << 2));
        float4 q3 = *(const float4*)(q3p + (d4 << 2));
        #pragma unroll
        for (int t = 0; t < 5; ++t) {
            float4 kv = *(const float4*)(ks + swz(t * 32 + lane, d4));
            DOT4A(acc[t][0], q0, kv);
            DOT4A(acc[t][1], q1, kv);
            DOT4A(acc[t][2], q2, kv);
            DOT4A(acc[t][3], q3, kv);
        }
    }

    const float scale = 0.08838834764831844f;
    float wsum[4];
    #pragma unroll
    for (int qi = 0; qi < 4; ++qi) {
        int iq = iqw + qi;
        float mm = -INFINITY;
        #pragma unroll
        for (int t = 0; t < 5; ++t) {
            int r = t * 32 + lane;
            int j = r - iq;
            int g = lo + r;
            bool valid = (j >= 0) && (j <= 128) && ((unsigned)g < SS);
            acc[t][qi] = valid ? acc[t][qi] * scale : NEG_INF_F;
            mm = fmaxf(mm, acc[t][qi]);
        }
        mm = fmaxf(mm, __shfl_xor_sync(0xffffffffu, mm, 1));
        mm = fmaxf(mm, __shfl_xor_sync(0xffffffffu, mm, 2));
        mm = fmaxf(mm, __shfl_xor_sync(0xffffffffu, mm, 4));
        mm = fmaxf(mm, __shfl_xor_sync(0xffffffffu, mm, 8));
        mm = fmaxf(mm, __shfl_xor_sync(0xffffffffu, mm, 16));
        float s = 0.f;
        #pragma unroll
        for (int t = 0; t < 5; ++t) {
            float e = __expf(acc[t][qi] - mm);
            acc[t][qi] = e;
            s += e;
        }
        s += __shfl_xor_sync(0xffffffffu, s, 1);
        s += __shfl_xor_sync(0xffffffffu, s, 2);
        s += __shfl_xor_sync(0xffffffffu, s, 4);
        s += __shfl_xor_sync(0xffffffffu, s, 8);
        s += __shfl_xor_sync(0xffffffffu, s, 16);
        wsum[qi] = s;
    }

    __syncthreads();

    float* pw = probs + wid * PWARP;
    for (int i = lane; i < PWARP; i += 32) pw[i] = 0.f;
    __syncwarp();
    #pragma unroll
    for (int qi = 0; qi < 4; ++qi) {
        int iq = iqw + qi;
        #pragma unroll
        for (int t = 0; t < 5; ++t) {
            int j = t * 32 + lane - iq;
            if (j >= -4 && j <= 131)
                pw[qi * PW + 4 + j] = acc[t][qi];
        }
    }
    __syncwarp();

    {
        float4 o0 = make_float4(0,0,0,0), o1 = o0, o2 = o0, o3 = o0;
        const float* p0b = pw + 0 * PW + 4;
        const float* p1b = pw + 1 * PW + 3;
        const float* p2b = pw + 2 * PW + 2;
        const float* p3b = pw + 3 * PW + 1;
        #pragma unroll 4
        for (int rr = 0; rr < 132; ++rr) {
            int g = lo + iqw + rr;
            int gc = min(max(g, 0), SS - 1);
            float4 vv = __ldg((const float4*)(vg + (size_t)gc * DD + (lane << 2)));
            float p0 = p0b[rr];
            float p1 = p1b[rr];
            float p2 = p2b[rr];
            float p3 = p3b[rr];
            OUT_FMA(o0, p0, vv);
            OUT_FMA(o1, p1, vv);
            OUT_FMA(o2, p2, vv);
            OUT_FMA(o3, p3, vv);
        }
        float inv0 = 1.0f / wsum[0];
        float inv1 = 1.0f / wsum[1];
        float inv2 = 1.0f / wsum[2];
        float inv3 = 1.0f / wsum[3];
        float* op = outp + ((size_t)b * SS + s0 + iqw) * DD + (lane << 2);
        *(float4*)(op + 0 * DD) = make_float4(o0.x*inv0, o0.y*inv0, o0.z*inv0, o0.w*inv0);
        *(float4*)(op + 1 * DD) = make_float4(o1.x*inv1, o1.y*inv1, o1.z*inv1, o1.w*inv1);
        *(float4*)(op + 2 * DD) = make_float4(o2.x*inv2, o2.y*inv2, o2.z*inv2, o2.w*inv2);
        *(float4*)(op + 3 * DD) = make_float4(o3.x*inv3, o3.y*inv3, o3.z*inv3, o3.w*inv3);
    }
}

extern "C" void kernel_launch(void* const* d_in, const int* in_sizes, int n_in,
                              void* d_out, int out_size)
{
    const float* x  = (const float*)d_in[0];
    const float* Wq = (const float*)d_in[1];
    const float* bq = (const float*)d_in[2];
    const float* Wk = (const float*)d_in[3];
    const float* bk = (const float*)d_in[4];
    const float* Wv = (const float*)d_in[5];
    const float* bv = (const float*)d_in[6];
    float* out = (float*)d_out;

    cudaFuncSetAttribute(qkv_mma_kernel,
                         cudaFuncAttributeMaxDynamicSharedMemorySize, QKV_SMEM);
    const int union_floats = (8 * PWARP > TQ * DD) ? 8 * PWARP : TQ * DD;
    const int attn_smem = (KROWS * DD + union_floats) * (int)sizeof(float);
    cudaFuncSetAttribute(attn_kernel,
                         cudaFuncAttributeMaxDynamicSharedMemorySize, attn_smem);

    wconv_kernel<<<dim3(3, 16), 256>>>(Wq, Wk, Wv);
    qkv_mma_kernel<<<BB * SS / 64, 256, QKV_SMEM>>>(x, bq, bk, bv);
    attn_kernel<<<BB * SS / TQ, 256, attn_smem>>>(out);
}

// round 8
// speedup vs baseline: 1.5481x; 1.0656x over previous
#include <cuda_runtime.h>
#include <cuda_bf16.h>
#include <math.h>
#include <stdint.h>

#define BB 2
#define SS 4096
#define DD 128
#define HALF 64
#define TQ 32
#define KROWS (TQ + 2*HALF)   /* 160 */
#define PW 136
#define PWARP (4*PW)
#define NEG_INF_F (-1e30f)

__device__ float g_q[BB*SS*DD];
__device__ float g_k[BB*SS*DD];
__device__ float g_v[BB*SS*DD];

#define S136 136               /* bf16 elems per row (272 B stride) */

// Pre-converted, pre-transposed W: Wt[n][k] as bf16 hi/lo, row stride S136.
__device__ __nv_bfloat16 g_wt_hi[3][128*S136];
__device__ __nv_bfloat16 g_wt_lo[3][128*S136];

__device__ __forceinline__ void mma16816(float* d, const uint32_t* a,
                                         const uint32_t* b) {
    asm volatile(
        "mma.sync.aligned.m16n8k16.row.col.f32.bf16.bf16.f32 "
        "{%0,%1,%2,%3}, {%4,%5,%6,%7}, {%8,%9}, {%0,%1,%2,%3};\n"
        : "+f"(d[0]), "+f"(d[1]), "+f"(d[2]), "+f"(d[3])
        : "r"(a[0]), "r"(a[1]), "r"(a[2]), "r"(a[3]), "r"(b[0]), "r"(b[1]));
}

__device__ __forceinline__ __nv_bfloat162 split_hi2(float x, float y) {
    return __nv_bfloat162(__float2bfloat16(x), __float2bfloat16(y));
}
__device__ __forceinline__ __nv_bfloat162 split_lo2(float x, float y) {
    float hx = __bfloat162float(__float2bfloat16(x));
    float hy = __bfloat162float(__float2bfloat16(y));
    return __nv_bfloat162(__float2bfloat16(x - hx), __float2bfloat16(y - hy));
}

// ============ one-shot W convert/transpose: 48 CTAs, one tile each ============

__global__ void __launch_bounds__(256) wconv_kernel(
    const float* __restrict__ Wq, const float* __restrict__ Wk,
    const float* __restrict__ Wv)
{
    const float* Wm[3] = {Wq, Wk, Wv};
    const float* Wg = Wm[blockIdx.x];
    __nv_bfloat16* whi = g_wt_hi[blockIdx.x];
    __nv_bfloat16* wlo = g_wt_lo[blockIdx.x];
    __shared__ float ts[32][33];
    const int tid = threadIdx.x;
    const int t   = blockIdx.y;
    const int tr  = t >> 2;
    const int tc  = t & 3;

    #pragma unroll
    for (int e = 0; e < 4; ++e) {
        int li = tid + e * 256;
        int r = li >> 5, c = li & 31;
        ts[r][c] = Wg[(size_t)(tr * 32 + r) * DD + tc * 32 + c];
    }
    __syncthreads();
    #pragma unroll
    for (int e = 0; e < 4; ++e) {
        int li = tid + e * 256;
        int n = li >> 5, k = li & 31;
        float v = ts[k][n];
        __nv_bfloat16 h = __float2bfloat16(v);
        int o = (tc * 32 + n) * S136 + tr * 32 + k;
        whi[o] = h;
        wlo[o] = __float2bfloat16(v - __bfloat162float(h));
    }
}

// ===================== QKV via mma.sync bf16 (unchanged) =====================

#define XTILE_B (64  * S136 * 2)
#define WTILE_B (128 * S136 * 2)
#define OFF_XHI 0
#define OFF_XLO (OFF_XHI + XTILE_B)
#define OFF_WHI (OFF_XLO + XTILE_B)
#define OFF_WLO (OFF_WHI + WTILE_B)
#define QKV_SMEM (OFF_WLO + WTILE_B)

__global__ void __launch_bounds__(256) qkv_mma_kernel(
    const float* __restrict__ x,
    const float* __restrict__ bq, const float* __restrict__ bk,
    const float* __restrict__ bv)
{
    extern __shared__ char sb[];
    const int tid  = threadIdx.x;
    const int wid  = tid >> 5;
    const int lane = tid & 31;
    const int row0 = blockIdx.x * 64;

    for (int idx = tid; idx < 64 * 64; idx += 256) {
        int r = idx >> 6, k = (idx & 63) << 1;
        float2 v = *(const float2*)(x + (size_t)(row0 + r) * DD + k);
        int off = (r * S136 + k) * 2;
        *(__nv_bfloat162*)(sb + OFF_XHI + off) = split_hi2(v.x, v.y);
        *(__nv_bfloat162*)(sb + OFF_XLO + off) = split_lo2(v.x, v.y);
    }

    const float* bias[3] = {bq, bk, bv};
    float* outm[3];
    outm[0] = g_q; outm[1] = g_k; outm[2] = g_v;

    const int mw = wid & 1;
    const int nw = wid >> 1;
    const int ar = lane >> 2;
    const int ac = (lane & 3) << 2;

    for (int m = 0; m < 3; ++m) {
        if (m > 0) __syncthreads();
        {
            const uint4* shi = (const uint4*)g_wt_hi[m];
            const uint4* slo = (const uint4*)g_wt_lo[m];
            uint4* dhi = (uint4*)(sb + OFF_WHI);
            uint4* dlo = (uint4*)(sb + OFF_WLO);
            for (int i = tid; i < WTILE_B / 16; i += 256) {
                dhi[i] = shi[i];
                dlo[i] = slo[i];
            }
        }
        __syncthreads();

        float acc[2][4][4];
        #pragma unroll
        for (int mt = 0; mt < 2; ++mt)
            #pragma unroll
            for (int nt = 0; nt < 4; ++nt)
                #pragma unroll
                for (int e = 0; e < 4; ++e) acc[mt][nt][e] = 0.f;

        #pragma unroll
        for (int ks = 0; ks < 8; ++ks) {
            const int kb = ks * 32;
            uint32_t ahi[2][4], alo[2][4];
            #pragma unroll
            for (int mt = 0; mt < 2; ++mt) {
                int abase = (mw * 32 + mt * 16 + ar) * 272 + kb + ac;
                ahi[mt][0] = *(const uint32_t*)(sb + OFF_XHI + abase);
                ahi[mt][1] = *(const uint32_t*)(sb + OFF_XHI + abase + 8*272);
                ahi[mt][2] = *(const uint32_t*)(sb + OFF_XHI + abase + 16);
                ahi[mt][3] = *(const uint32_t*)(sb + OFF_XHI + abase + 8*272 + 16);
                alo[mt][0] = *(const uint32_t*)(sb + OFF_XLO + abase);
                alo[mt][1] = *(const uint32_t*)(sb + OFF_XLO + abase + 8*272);
                alo[mt][2] = *(const uint32_t*)(sb + OFF_XLO + abase + 16);
                alo[mt][3] = *(const uint32_t*)(sb + OFF_XLO + abase + 8*272 + 16);
            }
            #pragma unroll
            for (int nt = 0; nt < 4; ++nt) {
                int bbase = (nw * 32 + nt * 8 + ar) * 272 + kb + ac;
                uint32_t bhi[2], blo[2];
                bhi[0] = *(const uint32_t*)(sb + OFF_WHI + bbase);
                bhi[1] = *(const uint32_t*)(sb + OFF_WHI + bbase + 16);
                blo[0] = *(const uint32_t*)(sb + OFF_WLO + bbase);
                blo[1] = *(const uint32_t*)(sb + OFF_WLO + bbase + 16);
                #pragma unroll
                for (int mt = 0; mt < 2; ++mt) {
                    mma16816(acc[mt][nt], ahi[mt], bhi);
                    mma16816(acc[mt][nt], ahi[mt], blo);
                    mma16816(acc[mt][nt], alo[mt], bhi);
                }
            }
        }

        const float* bp = bias[m];
        float* og = outm[m];
        #pragma unroll
        for (int mt = 0; mt < 2; ++mt) {
            int grow = row0 + mw * 32 + mt * 16 + ar;
            #pragma unroll
            for (int nt = 0; nt < 4; ++nt) {
                int c = nw * 32 + nt * 8 + ((lane & 3) << 1);
                float2 b2 = *(const float2*)(bp + c);
                float2 lo = make_float2(acc[mt][nt][0] + b2.x,
                                        acc[mt][nt][1] + b2.y);
                float2 hi = make_float2(acc[mt][nt][2] + b2.x,
                                        acc[mt][nt][3] + b2.y);
                *(float2*)(og + (size_t)grow * DD + c)       = lo;
                *(float2*)(og + (size_t)(grow + 8) * DD + c) = hi;
            }
        }
    }
}

// ============ attention: HMMA scores + scalar softmax/output ============
// smem layout (bytes):
//   [0,       43520)  k_hi  (160 x 136 bf16)       | sc (32x164 f32) overlays
//   [43520,   87040)  k_lo                         |   k_lo after score MMA
//   [87040,   95744)  q_hi  (32 x 136 bf16)        | probs (8 warps x 544 f32)
//   [95744,  104448)  q_lo                         |   overlays q after MMA

#define AT_KHI 0
#define AT_KLO 43520
#define AT_QHI 87040
#define AT_QLO 95744
#define AT_SC  AT_KLO            /* fp32 scores, stride 164 floats */
#define AT_PR  AT_QHI            /* probs strips */
#define SCST 164
#define ATTN_SMEM 104448

#define OUT_FMA(A, P, VV) \
    A.x = fmaf(P, VV.x, A.x); A.y = fmaf(P, VV.y, A.y); \
    A.z = fmaf(P, VV.z, A.z); A.w = fmaf(P, VV.w, A.w);

__global__ void __launch_bounds__(256, 2) attn_kernel(float* __restrict__ outp)
{
    extern __shared__ char sb[];
    const int tid  = threadIdx.x;
    const int wid  = tid >> 5;
    const int lane = tid & 31;
    const int blk  = blockIdx.x;
    const int b    = blk >> 7;
    const int s0   = (blk & 127) * TQ;
    const int lo   = s0 - HALF;

    const float* kg = g_k + (size_t)b * SS * DD;
    const float* vg = g_v + (size_t)b * SS * DD;
    const float* qg = g_q + (size_t)b * SS * DD;

    // ---- load + split k window (zero-fill OOB rows) ----
    for (int idx = tid; idx < KROWS * 64; idx += 256) {
        int r = idx >> 6, d = (idx & 63) << 1;
        int g = lo + r;
        float2 v = make_float2(0.f, 0.f);
        if ((unsigned)g < SS)
            v = *(const float2*)(kg + (size_t)g * DD + d);
        int off = (r * S136 + d) * 2;
        *(__nv_bfloat162*)(sb + AT_KHI + off) = split_hi2(v.x, v.y);
        *(__nv_bfloat162*)(sb + AT_KLO + off) = split_lo2(v.x, v.y);
    }
    // ---- load + split q tile ----
    for (int idx = tid; idx < TQ * 64; idx += 256) {
        int r = idx >> 6, d = (idx & 63) << 1;
        float2 v = *(const float2*)(qg + (size_t)(s0 + r) * DD + d);
        int off = (r * S136 + d) * 2;
        *(__nv_bfloat162*)(sb + AT_QHI + off) = split_hi2(v.x, v.y);
        *(__nv_bfloat162*)(sb + AT_QLO + off) = split_lo2(v.x, v.y);
    }
    __syncthreads();

    // ---- HMMA scores: warp -> m16 tile (wid&1) x 40 key-cols ((wid>>1)*40) ----
    const int mt = wid & 1;
    const int ng = wid >> 1;
    const int ar = lane >> 2;
    const int ac = (lane & 3) << 2;

    float sacc[5][4];
    #pragma unroll
    for (int nt = 0; nt < 5; ++nt)
        #pragma unroll
        for (int e = 0; e < 4; ++e) sacc[nt][e] = 0.f;

    #pragma unroll
    for (int ks = 0; ks < 8; ++ks) {
        const int kb = ks * 32;
        const int abase = (mt * 16 + ar) * 272 + kb + ac;
        uint32_t ahi[4], alo[4];
        ahi[0] = *(const uint32_t*)(sb + AT_QHI + abase);
        ahi[1] = *(const uint32_t*)(sb + AT_QHI + abase + 8*272);
        ahi[2] = *(const uint32_t*)(sb + AT_QHI + abase + 16);
        ahi[3] = *(const uint32_t*)(sb + AT_QHI + abase + 8*272 + 16);
        alo[0] = *(const uint32_t*)(sb + AT_QLO + abase);
        alo[1] = *(const uint32_t*)(sb + AT_QLO + abase + 8*272);
        alo[2] = *(const uint32_t*)(sb + AT_QLO + abase + 16);
        alo[3] = *(const uint32_t*)(sb + AT_QLO + abase + 8*272 + 16);
        #pragma unroll
        for (int nt = 0; nt < 5; ++nt) {
            int bbase = (ng * 40 + nt * 8 + ar) * 272 + kb + ac;
            uint32_t bhi[2], blo[2];
            bhi[0] = *(const uint32_t*)(sb + AT_KHI + bbase);
            bhi[1] = *(const uint32_t*)(sb + AT_KHI + bbase + 16);
            blo[0] = *(const uint32_t*)(sb + AT_KLO + bbase);
            blo[1] = *(const uint32_t*)(sb + AT_KLO + bbase + 16);
            mma16816(sacc[nt], ahi, bhi);
            mma16816(sacc[nt], ahi, blo);
            mma16816(sacc[nt], alo, bhi);
        }
    }
    __syncthreads();   // all k/q smem reads done; sc may overlay k_lo

    // ---- store score fragments to sc[row][col] (stride SCST) ----
    {
        float* sc = (float*)(sb + AT_SC);
        #pragma unroll
        for (int nt = 0; nt < 5; ++nt) {
            int row = mt * 16 + ar;
            int col = ng * 40 + nt * 8 + ((lane & 3) << 1);
            *(float2*)(sc + row * SCST + col)       = make_float2(sacc[nt][0], sacc[nt][1]);
            *(float2*)(sc + (row + 8) * SCST + col) = make_float2(sacc[nt][2], sacc[nt][3]);
        }
    }
    __syncthreads();

    // ---- per-warp: reload scores for 4 queries, mask + softmax (as R3) ----
    const int iqw = wid << 2;
    float acc[5][4];
    {
        const float* sc = (const float*)(sb + AT_SC);
        #pragma unroll
        for (int qi = 0; qi < 4; ++qi)
            #pragma unroll
            for (int t = 0; t < 5; ++t)
                acc[t][qi] = sc[(iqw + qi) * SCST + t * 32 + lane];
    }

    const float scale = 0.08838834764831844f;
    float wsum[4];
    #pragma unroll
    for (int qi = 0; qi < 4; ++qi) {
        int iq = iqw + qi;
        float mm = -INFINITY;
        #pragma unroll
        for (int t = 0; t < 5; ++t) {
            int r = t * 32 + lane;
            int j = r - iq;
            int g = lo + r;
            bool valid = (j >= 0) && (j <= 128) && ((unsigned)g < SS);
            acc[t][qi] = valid ? acc[t][qi] * scale : NEG_INF_F;
            mm = fmaxf(mm, acc[t][qi]);
        }
        mm = fmaxf(mm, __shfl_xor_sync(0xffffffffu, mm, 1));
        mm = fmaxf(mm, __shfl_xor_sync(0xffffffffu, mm, 2));
        mm = fmaxf(mm, __shfl_xor_sync(0xffffffffu, mm, 4));
        mm = fmaxf(mm, __shfl_xor_sync(0xffffffffu, mm, 8));
        mm = fmaxf(mm, __shfl_xor_sync(0xffffffffu, mm, 16));
        float s = 0.f;
        #pragma unroll
        for (int t = 0; t < 5; ++t) {
            float e = __expf(acc[t][qi] - mm);
            acc[t][qi] = e;
            s += e;
        }
        s += __shfl_xor_sync(0xffffffffu, s, 1);
        s += __shfl_xor_sync(0xffffffffu, s, 2);
        s += __shfl_xor_sync(0xffffffffu, s, 4);
        s += __shfl_xor_sync(0xffffffffu, s, 8);
        s += __shfl_xor_sync(0xffffffffu, s, 16);
        wsum[qi] = s;
    }

    // ---- write probs to per-warp strip overlaying q (q dead after MMA) ----
    float* pw = (float*)(sb + AT_PR) + wid * PWARP;
    for (int i = lane; i < PWARP; i += 32) pw[i] = 0.f;
    __syncwarp();
    #pragma unroll
    for (int qi = 0; qi < 4; ++qi) {
        int iq = iqw + qi;
        #pragma unroll
        for (int t = 0; t < 5; ++t) {
            int j = t * 32 + lane - iq;
            if (j >= -4 && j <= 131)
                pw[qi * PW + 4 + j] = acc[t][qi];
        }
    }
    __syncwarp();

    // ---- output: lane = dim chunk; v streamed from global (L1 hot) ----
    {
        float4 o0 = make_float4(0,0,0,0), o1 = o0, o2 = o0, o3 = o0;
        const float* p0b = pw + 0 * PW + 4;
        const float* p1b = pw + 1 * PW + 3;
        const float* p2b = pw + 2 * PW + 2;
        const float* p3b = pw + 3 * PW + 1;
        #pragma unroll 4
        for (int rr = 0; rr < 132; ++rr) {
            int g = lo + iqw + rr;
            int gc = min(max(g, 0), SS - 1);
            float4 vv = __ldg((const float4*)(vg + (size_t)gc * DD + (lane << 2)));
            float p0 = p0b[rr];
            float p1 = p1b[rr];
            float p2 = p2b[rr];
            float p3 = p3b[rr];
            OUT_FMA(o0, p0, vv);
            OUT_FMA(o1, p1, vv);
            OUT_FMA(o2, p2, vv);
            OUT_FMA(o3, p3, vv);
        }
        float inv0 = 1.0f / wsum[0];
        float inv1 = 1.0f / wsum[1];
        float inv2 = 1.0f / wsum[2];
        float inv3 = 1.0f / wsum[3];
        float* op = outp + ((size_t)b * SS + s0 + iqw) * DD + (lane << 2);
        *(float4*)(op + 0 * DD) = make_float4(o0.x*inv0, o0.y*inv0, o0.z*inv0, o0.w*inv0);
        *(float4*)(op + 1 * DD) = make_float4(o1.x*inv1, o1.y*inv1, o1.z*inv1, o1.w*inv1);
        *(float4*)(op + 2 * DD) = make_float4(o2.x*inv2, o2.y*inv2, o2.z*inv2, o2.w*inv2);
        *(float4*)(op + 3 * DD) = make_float4(o3.x*inv3, o3.y*inv3, o3.z*inv3, o3.w*inv3);
    }
}

extern "C" void kernel_launch(void* const* d_in, const int* in_sizes, int n_in,
                              void* d_out, int out_size)
{
    const float* x  = (const float*)d_in[0];
    const float* Wq = (const float*)d_in[1];
    const float* bq = (const float*)d_in[2];
    const float* Wk = (const float*)d_in[3];
    const float* bk = (const float*)d_in[4];
    const float* Wv = (const float*)d_in[5];
    const float* bv = (const float*)d_in[6];
    float* out = (float*)d_out;

    cudaFuncSetAttribute(qkv_mma_kernel,
                         cudaFuncAttributeMaxDynamicSharedMemorySize, QKV_SMEM);
    cudaFuncSetAttribute(attn_kernel,
                         cudaFuncAttributeMaxDynamicSharedMemorySize, ATTN_SMEM);

    wconv_kernel<<<dim3(3, 16), 256>>>(Wq, Wk, Wv);
    qkv_mma_kernel<<<BB * SS / 64, 256, QKV_SMEM>>>(x, bq, bk, bv);
    attn_kernel<<<BB * SS / TQ, 256, ATTN_SMEM>>>(out);
}